// round 8
// baseline (speedup 1.0000x reference)
#include <cuda_runtime.h>

#define N_AG 512
#define T_STEPS 12
#define NB 128
#define NT 512

// ------------------------- cross-block scratch -------------------------
__device__ float2 g_B2buf[2][32 * N_AG];       // [buf][dd*512 + j] = (B[j][2dd], B[j][2dd+1])
__device__ unsigned g_cnt[T_STEPS];
__device__ volatile unsigned g_flag[T_STEPS];
__device__ unsigned g_depart;

__device__ __forceinline__ float sigf(float x) { return 1.f / (1.f + __expf(-x)); }

__global__ __launch_bounds__(NT, 1) void k_fused(
    const float* __restrict__ p, const float* __restrict__ c, const float* __restrict__ z,
    const float* __restrict__ obs, const float* __restrict__ eps, const float* __restrict__ c0,
    const int* __restrict__ nei,
    const float* __restrict__ W_in, const float* __restrict__ b_in,
    const float* __restrict__ W_ih, const float* __restrict__ W_hh,
    const float* __restrict__ b_ih, const float* __restrict__ b_hh,
    const float* __restrict__ W_m, const float* __restrict__ b_m,
    const float* __restrict__ W_v, const float* __restrict__ b_v,
    const float* __restrict__ W_zh, const float* __restrict__ b_zh,
    const float* __restrict__ W_se, const float* __restrict__ b_se,
    const float* __restrict__ W1, const float* __restrict__ b1,
    const float* __restrict__ W2, const float* __restrict__ b2,
    float* __restrict__ out)
{
    __shared__ float4 w2a[32][2];      // W2[2dd][4h..4h+3]
    __shared__ float4 w2b[32][2];      // W2[2dd+1][4h..4h+3]
    __shared__ float  sh_Mse0[64];
    __shared__ float  sh_Mse1[64];
    __shared__ float  sh_b1[64];
    __shared__ float  sh_b2[8];
    __shared__ float2 Ash[4][32];      // A[i][d] pairs, per agent
    __shared__ float  sh_h[4][8], sh_cl[4][8], sh_ctx[4][8];
    __shared__ float2 sh_pos[4], sh_prev[4];
    __shared__ float  red[16][8];      // per-warp partial maxes
    __shared__ unsigned short sh_list[4][N_AG];   // compacted active-j lists
    __shared__ int    sh_cnt[4];

    const int tid  = threadIdx.x;
    const int warp = tid >> 5;
    const int lane = tid & 31;
    const int blk  = blockIdx.x;

    // ---------------- preload constants ----------------
    if (tid < 64) {
        int d = tid;
        float m0 = 0.f, m1 = 0.f, bb = b1[d];
        for (int u = 0; u < 32; u++) {
            float w = W1[u * 64 + d];
            m0 += W_se[u] * w;
            m1 += W_se[32 + u] * w;
            bb += b_se[u] * w;
        }
        sh_Mse0[d] = m0; sh_Mse1[d] = m1; sh_b1[d] = bb;
    } else if (tid < 192) {
        int e = tid - 64;               // 128 entries: dd(32) x r(2) x h(2)
        int dd = e >> 2, r = (e >> 1) & 1, hh = e & 1;
        const float* row = W2 + (2 * dd + r) * 8 + 4 * hh;
        float4 v = make_float4(row[0], row[1], row[2], row[3]);
        if (r == 0) w2a[dd][hh] = v; else w2b[dd][hh] = v;
    } else if (tid < 200) {
        sh_b2[tid - 192] = b2[tid - 192];
    }

    // ---------------- init per-agent state (warps 0..3) ----------------
    if (warp < 4) {
        int i = blk * 4 + warp;
        if (lane < 8) {
            float z0 = z[2 * i], z1 = z[2 * i + 1];
            sh_h[warp][lane]   = z0 * W_zh[lane] + z1 * W_zh[8 + lane] + b_zh[lane];
            sh_cl[warp][lane]  = c0[i * 8 + lane];
            sh_ctx[warp][lane] = 0.f;
        }
        if (lane == 0) {
            sh_pos[warp]  = make_float2(obs[(7 * N_AG + i) * 2], obs[(7 * N_AG + i) * 2 + 1]);
            sh_prev[warp] = make_float2(p[2 * i], p[2 * i + 1]);
        }
    }
    __syncthreads();

    for (int t = 0; t <= T_STEPS; t++) {
        // ================= step phase (warps 0..3) || compaction (warps 4..7) =======
        if (warp < 4) {
            int a = warp;
            int i = blk * 4 + a;

            if (t >= 1 && lane < 8) {
                float v = fmaxf(fmaxf(red[a * 4 + 0][lane], red[a * 4 + 1][lane]),
                                fmaxf(red[a * 4 + 2][lane], red[a * 4 + 3][lane]));
                sh_ctx[a][lane] = v;
            }
            __syncwarp();

            float h[8], ctx[8];
#pragma unroll
            for (int u = 0; u < 8; u++) { h[u] = sh_h[a][u]; ctx[u] = sh_ctx[a][u]; }
            float cl8 = sh_cl[a][lane & 7];

            float pos0, pos1, pv0, pv1;
            if (t > 0) {
                int tc = t - 1;
                float mu[2], lv[2];
#pragma unroll
                for (int m = 0; m < 2; m++) {
                    float s  = b_m[m];
                    float s2 = b_v[m];
#pragma unroll
                    for (int u = 0; u < 4; u++) {
                        s  += h[u]     * W_m[u * 2 + m];
                        s2 += h[4 + u] * W_v[u * 2 + m];
                    }
#pragma unroll
                    for (int k = 0; k < 8; k++) {
                        s  += ctx[k] * W_m[(4 + k) * 2 + m];
                        s2 += ctx[k] * W_v[(4 + k) * 2 + m];
                    }
                    mu[m] = s; lv[m] = s2;
                }
                float e0 = eps[(tc * N_AG + i) * 2];
                float e1 = eps[(tc * N_AG + i) * 2 + 1];
                float p0 = mu[0] + e0 * expf(0.5f * lv[0]);
                float p1 = mu[1] + e1 * expf(0.5f * lv[1]);
                pv0 = p0; pv1 = p1;
                pos0 = sh_pos[a].x + p0;
                pos1 = sh_pos[a].y + p1;
                if (lane == 0) {
                    out[tc * 1024 + 2 * i]             = p0;
                    out[tc * 1024 + 2 * i + 1]         = p1;
                    out[12288 + tc * 1024 + 2 * i]     = mu[0];
                    out[12288 + tc * 1024 + 2 * i + 1] = mu[1];
                    out[24576 + tc * 1024 + 2 * i]     = lv[0];
                    out[24576 + tc * 1024 + 2 * i + 1] = lv[1];
                    sh_prev[a] = make_float2(pv0, pv1);
                    sh_pos[a]  = make_float2(pos0, pos1);
                }
            } else {
                pv0 = sh_prev[a].x; pv1 = sh_prev[a].y;
                pos0 = sh_pos[a].x; pos1 = sh_pos[a].y;
            }

            if (t < T_STEPS) {
                float x[20];
#pragma unroll
                for (int u = 0; u < 8; u++) x[u] = ctx[u];
                x[8] = pv0; x[9] = pv1;
#pragma unroll
                for (int u = 0; u < 8; u++) x[10 + u] = c[i * 8 + u];
                x[18] = z[2 * i]; x[19] = z[2 * i + 1];

                float xr = 0.f;
                if (lane < 16) {
                    float s = b_in[lane];
#pragma unroll
                    for (int v = 0; v < 20; v++) s += x[v] * W_in[v * 16 + lane];
                    xr = fmaxf(s, 0.f);
                }

                float g = b_ih[lane] + b_hh[lane];
#pragma unroll
                for (int u = 0; u < 16; u++) {
                    float xu = __shfl_sync(0xffffffffu, xr, u);
                    g += xu * W_ih[u * 32 + lane];
                }
#pragma unroll
                for (int u = 0; u < 8; u++) g += h[u] * W_hh[u * 32 + lane];

                int u8 = lane & 7;
                float gi = __shfl_sync(0xffffffffu, g, u8);
                float gf = __shfl_sync(0xffffffffu, g, u8 + 8);
                float gg = __shfl_sync(0xffffffffu, g, u8 + 16);
                float go = __shfl_sync(0xffffffffu, g, u8 + 24);
                float cln = sigf(gf) * cl8 + sigf(gi) * tanhf(gg);
                float hn  = sigf(go) * tanhf(cln);
                if (lane < 8) {
                    sh_cl[a][lane] = cln;
                    sh_h[a][lane]  = hn;
                }
                float hw[8];
#pragma unroll
                for (int u = 0; u < 8; u++) hw[u] = __shfl_sync(0xffffffffu, hn, u);

                // A/B precompute: lane owns d-pair (2l, 2l+1)
                int d = 2 * lane;
                float m0x = sh_Mse0[d],  m0y = sh_Mse0[d + 1];
                float m1x = sh_Mse1[d],  m1y = sh_Mse1[d + 1];
                float bx = pos0 * m0x + pos1 * m1x;
                float by = pos0 * m0y + pos1 * m1y;
                float Ax = sh_b1[d] + bx,     Ay = sh_b1[d + 1] + by;
                float Bx = -bx,               By = -by;
#pragma unroll
                for (int u = 0; u < 8; u++) {
                    float2 wA = *(const float2*)(W1 + (40 + u) * 64 + d);
                    float2 wB = *(const float2*)(W1 + (32 + u) * 64 + d);
                    Ax = fmaf(hw[u], wA.x, Ax); Ay = fmaf(hw[u], wA.y, Ay);
                    Bx = fmaf(hw[u], wB.x, Bx); By = fmaf(hw[u], wB.y, By);
                }
                Ash[a][lane] = make_float2(Ax, Ay);
                g_B2buf[t & 1][lane * N_AG + i] = make_float2(Bx, By);
            }
        } else if (warp < 8 && t < T_STEPS) {
            // ---- compaction of nei row for step t (one warp per agent) ----
            int a = warp - 4;
            int i = blk * 4 + a;
            const int* neirow = nei + ((long)t * N_AG + i) * N_AG;
            int cnt = 0;
#pragma unroll 4
            for (int g = 0; g < 16; g++) {
                int j0 = g * 32 + lane;
                int nv = neirow[j0];
                unsigned bal = __ballot_sync(0xffffffffu, nv > 0);
                if (nv > 0) {
                    int pos = cnt + __popc(bal & ((1u << lane) - 1u));
                    sh_list[a][pos] = (unsigned short)j0;
                }
                cnt += __popc(bal);
            }
            if (lane == 0) sh_cnt[a] = cnt;
        }
        if (t == T_STEPS) break;
        __syncthreads();    // Ash/B2/list writes done, red consumed

        // ================= grid barrier t =================
        if (tid == 0) {
            __threadfence();
            unsigned v = atomicAdd(&g_cnt[t], 1u);
            if (v == NB - 1) {
                if (t > 0) { g_cnt[t - 1] = 0; g_flag[t - 1] = 0; }
                g_flag[t] = 1;
                __threadfence();
            } else {
                while (g_flag[t] == 0) { }
            }
            __threadfence();
        }
        __syncthreads();

        // ================= pool phase (all 16 warps), compacted =================
        {
            int a = warp >> 2;
            int wq = warp & 3;
            int cnt = sh_cnt[a];
            const float2* Bv = (const float2*)g_B2buf[t & 1];

            float m[8];
#pragma unroll
            for (int k = 0; k < 8; k++) m[k] = 0.f;   // ph>=0 and -inf->0 => 0 init

            for (int base = wq * 32; base < cnt; base += 128) {
                int slot = base + lane;
                bool valid = slot < cnt;
                int jl = sh_list[a][valid ? slot : (cnt - 1)];

                float acc[8];
#pragma unroll
                for (int k = 0; k < 8; k++) acc[k] = 0.f;

#pragma unroll 4
                for (int dd = 0; dd < 32; dd++) {
                    float2 av = Ash[a][dd];
                    float2 bv = Bv[dd * N_AG + jl];
                    float tx = fmaxf(av.x + bv.x, 0.f);
                    float ty = fmaxf(av.y + bv.y, 0.f);
                    float4 wa0 = w2a[dd][0], wa1 = w2a[dd][1];
                    float4 wb0 = w2b[dd][0], wb1 = w2b[dd][1];
                    acc[0] = fmaf(tx, wa0.x, fmaf(ty, wb0.x, acc[0]));
                    acc[1] = fmaf(tx, wa0.y, fmaf(ty, wb0.y, acc[1]));
                    acc[2] = fmaf(tx, wa0.z, fmaf(ty, wb0.z, acc[2]));
                    acc[3] = fmaf(tx, wa0.w, fmaf(ty, wb0.w, acc[3]));
                    acc[4] = fmaf(tx, wa1.x, fmaf(ty, wb1.x, acc[4]));
                    acc[5] = fmaf(tx, wa1.y, fmaf(ty, wb1.y, acc[5]));
                    acc[6] = fmaf(tx, wa1.z, fmaf(ty, wb1.z, acc[6]));
                    acc[7] = fmaf(tx, wa1.w, fmaf(ty, wb1.w, acc[7]));
                }
#pragma unroll
                for (int k = 0; k < 8; k++) {
                    float s = fmaxf(acc[k] + sh_b2[k], 0.f);
                    if (valid) m[k] = fmaxf(m[k], s);
                }
            }

#pragma unroll
            for (int k = 0; k < 8; k++) {
                float v = m[k];
                v = fmaxf(v, __shfl_xor_sync(0xffffffffu, v, 16));
                v = fmaxf(v, __shfl_xor_sync(0xffffffffu, v, 8));
                v = fmaxf(v, __shfl_xor_sync(0xffffffffu, v, 4));
                v = fmaxf(v, __shfl_xor_sync(0xffffffffu, v, 2));
                v = fmaxf(v, __shfl_xor_sync(0xffffffffu, v, 1));
                m[k] = v;
            }
            if (lane < 8) red[warp][lane] = m[lane];
        }
        __syncthreads();    // red ready for next step; Ash/list free to overwrite
    }

    // ---------------- replay-safe cleanup of last barrier ----------------
    if (tid == 0) {
        __threadfence();
        unsigned d = atomicAdd(&g_depart, 1u);
        if (d == NB - 1) {
            g_cnt[T_STEPS - 1] = 0;
            g_flag[T_STEPS - 1] = 0;
            g_depart = 0;
            __threadfence();
        }
    }
}

// ------------------------- launch -------------------------
extern "C" void kernel_launch(void* const* d_in, const int* in_sizes, int n_in,
                              void* d_out, int out_size)
{
    const float* p    = (const float*)d_in[0];
    const float* c    = (const float*)d_in[1];
    const float* z    = (const float*)d_in[2];
    const float* obs  = (const float*)d_in[3];
    const float* eps  = (const float*)d_in[4];
    const float* c0   = (const float*)d_in[5];
    const int*   nei  = (const int*)d_in[6];
    const float* W_in = (const float*)d_in[8];
    const float* b_in = (const float*)d_in[9];
    const float* W_ih = (const float*)d_in[10];
    const float* W_hh = (const float*)d_in[11];
    const float* b_ih = (const float*)d_in[12];
    const float* b_hh = (const float*)d_in[13];
    const float* W_m  = (const float*)d_in[14];
    const float* b_m  = (const float*)d_in[15];
    const float* W_v  = (const float*)d_in[16];
    const float* b_v  = (const float*)d_in[17];
    const float* W_zh = (const float*)d_in[18];
    const float* b_zh = (const float*)d_in[19];
    const float* W_se = (const float*)d_in[20];
    const float* b_se = (const float*)d_in[21];
    const float* W1   = (const float*)d_in[22];
    const float* b1   = (const float*)d_in[23];
    const float* W2   = (const float*)d_in[24];
    const float* b2   = (const float*)d_in[25];
    float* out = (float*)d_out;

    k_fused<<<NB, NT>>>(p, c, z, obs, eps, c0, nei,
                        W_in, b_in, W_ih, W_hh, b_ih, b_hh,
                        W_m, b_m, W_v, b_v, W_zh, b_zh,
                        W_se, b_se, W1, b1, W2, b2, out);
}